// round 1
// baseline (speedup 1.0000x reference)
#include <cuda_runtime.h>

// Problem constants (fixed shapes from reference)
#define N_ROWS 131072
#define F_IN   256
#define N_SRC  32
#define F_OUT  64
#define W_COLS (N_SRC * F_OUT)   // 2048

// GEMM tiling
#define BM 128
#define BK 32
#define NTHREADS 256
#define PERM_SIZE (N_ROWS + N_SRC * BM)       // padded permutation upper bound
#define MAX_TILES (N_ROWS / BM + N_SRC)       // 1024 + 32 = 1056

// Scratch (no cudaMalloc allowed)
__device__ int g_counts[N_SRC];
__device__ int g_off[N_SRC + 1];
__device__ int g_cursor[N_SRC];
__device__ int g_perm[PERM_SIZE];

// ---------------------------------------------------------------------------
// Pass 0: reset scratch (graph is replayed; must be idempotent per launch)
// ---------------------------------------------------------------------------
__global__ void k_init() {
    int i = blockIdx.x * blockDim.x + threadIdx.x;
    if (i < PERM_SIZE) g_perm[i] = -1;
    if (i < N_SRC) g_counts[i] = 0;
}

// ---------------------------------------------------------------------------
// Pass 1: histogram of source ids
// ---------------------------------------------------------------------------
__global__ void k_hist(const int* __restrict__ src) {
    __shared__ int bins[N_SRC];
    if (threadIdx.x < N_SRC) bins[threadIdx.x] = 0;
    __syncthreads();
    for (int i = blockIdx.x * blockDim.x + threadIdx.x; i < N_ROWS;
         i += gridDim.x * blockDim.x) {
        atomicAdd(&bins[src[i]], 1);
    }
    __syncthreads();
    if (threadIdx.x < N_SRC) atomicAdd(&g_counts[threadIdx.x], bins[threadIdx.x]);
}

// ---------------------------------------------------------------------------
// Pass 2: padded exclusive scan (32 elements, trivial serial)
// Buckets padded to multiples of BM so every GEMM tile has exactly one source.
// ---------------------------------------------------------------------------
__global__ void k_scan() {
    if (threadIdx.x == 0 && blockIdx.x == 0) {
        int acc = 0;
        for (int s = 0; s < N_SRC; s++) {
            g_off[s] = acc;
            g_cursor[s] = acc;
            int padded = ((g_counts[s] + BM - 1) / BM) * BM;
            acc += padded;
        }
        g_off[N_SRC] = acc;
    }
}

// ---------------------------------------------------------------------------
// Pass 3: scatter row indices into source-sorted permutation
// (order within a bucket is nondeterministic but output is row-keyed -> fine)
// ---------------------------------------------------------------------------
__global__ void k_scatter(const int* __restrict__ src) {
    int i = blockIdx.x * blockDim.x + threadIdx.x;
    if (i < N_ROWS) {
        int pos = atomicAdd(&g_cursor[src[i]], 1);
        g_perm[pos] = i;
    }
}

// ---------------------------------------------------------------------------
// Pass 4: tiled SGEMM over source-sorted rows.
// Each block: 128 rows (one source) x 64 output features, K = 256 in 8 chunks.
// Thread micro-tile: 4 rows x 8 cols (acc[4][8]).
// ---------------------------------------------------------------------------
__global__ void __launch_bounds__(NTHREADS)
k_gemm(const float* __restrict__ x, const float* __restrict__ W,
       const float* __restrict__ b, float* __restrict__ out) {
    __shared__ float  xs[BM * (BK + 1)];     // padded: bank-conflict free
    __shared__ float4 ws4[BK * (F_OUT / 4)]; // ws[kk][f] as float4
    __shared__ int    sperm[BM];
    __shared__ int    s_src;

    const int tile = blockIdx.x;
    const int tstart = tile * BM;
    const int tid = threadIdx.x;

    if (tid == 0) {
        int srcid = -1;
        int total = g_off[N_SRC];
        if (tstart < total) {
            #pragma unroll
            for (int s = 0; s < N_SRC; s++) {
                if (tstart >= g_off[s] && tstart < g_off[s + 1]) { srcid = s; break; }
            }
        }
        s_src = srcid;
    }
    __syncthreads();
    const int src = s_src;
    if (src < 0) return;   // tile beyond padded total (uniform exit)

    for (int i = tid; i < BM; i += NTHREADS) sperm[i] = g_perm[tstart + i];
    __syncthreads();

    const int tc = tid & 7;    // col group: cols tc*8 .. tc*8+7
    const int tr = tid >> 3;   // row group: rows tr*4 .. tr*4+3

    float acc[4][8];
    #pragma unroll
    for (int i = 0; i < 4; i++)
        #pragma unroll
        for (int j = 0; j < 8; j++) acc[i][j] = 0.0f;

    #pragma unroll 1
    for (int kt = 0; kt < F_IN / BK; kt++) {
        const int k0 = kt * BK;

        // Stage x tile: 128 rows x 32 k = 1024 float4; 4 per thread.
        #pragma unroll
        for (int q = 0; q < 4; q++) {
            int idx = tid + q * NTHREADS;
            int row = idx >> 3;
            int seg = idx & 7;
            int prow = sperm[row];
            float4 v = make_float4(0.f, 0.f, 0.f, 0.f);
            if (prow >= 0)
                v = *reinterpret_cast<const float4*>(
                        x + (size_t)prow * F_IN + k0 + seg * 4);
            float* dst = &xs[row * (BK + 1) + seg * 4];
            dst[0] = v.x; dst[1] = v.y; dst[2] = v.z; dst[3] = v.w;
        }
        // Stage W tile: 32 k x 64 f = 512 float4; 2 per thread.
        #pragma unroll
        for (int q = 0; q < 2; q++) {
            int v = tid + q * NTHREADS;
            int kk = v >> 4;
            int f4 = v & 15;
            ws4[kk * 16 + f4] = *reinterpret_cast<const float4*>(
                W + (size_t)(k0 + kk) * W_COLS + src * F_OUT + f4 * 4);
        }
        __syncthreads();

        #pragma unroll
        for (int kk = 0; kk < BK; kk++) {
            float a[4];
            #pragma unroll
            for (int i = 0; i < 4; i++)
                a[i] = xs[(tr * 4 + i) * (BK + 1) + kk];
            float4 w0 = ws4[kk * 16 + tc * 2];
            float4 w1 = ws4[kk * 16 + tc * 2 + 1];
            #pragma unroll
            for (int i = 0; i < 4; i++) {
                acc[i][0] += a[i] * w0.x;
                acc[i][1] += a[i] * w0.y;
                acc[i][2] += a[i] * w0.z;
                acc[i][3] += a[i] * w0.w;
                acc[i][4] += a[i] * w1.x;
                acc[i][5] += a[i] * w1.y;
                acc[i][6] += a[i] * w1.z;
                acc[i][7] += a[i] * w1.w;
            }
        }
        __syncthreads();
    }

    // Bias + store (b is zeros in the reference, but honor it anyway)
    float4 b0 = *reinterpret_cast<const float4*>(b + src * F_OUT + tc * 8);
    float4 b1 = *reinterpret_cast<const float4*>(b + src * F_OUT + tc * 8 + 4);
    #pragma unroll
    for (int i = 0; i < 4; i++) {
        int prow = sperm[tr * 4 + i];
        if (prow < 0) continue;
        float4 o0 = make_float4(acc[i][0] + b0.x, acc[i][1] + b0.y,
                                acc[i][2] + b0.z, acc[i][3] + b0.w);
        float4 o1 = make_float4(acc[i][4] + b1.x, acc[i][5] + b1.y,
                                acc[i][6] + b1.z, acc[i][7] + b1.w);
        float* orow = out + (size_t)prow * F_OUT + tc * 8;
        *reinterpret_cast<float4*>(orow)     = o0;
        *reinterpret_cast<float4*>(orow + 4) = o1;
    }
}

// ---------------------------------------------------------------------------
extern "C" void kernel_launch(void* const* d_in, const int* in_sizes, int n_in,
                              void* d_out, int out_size) {
    const float* x   = (const float*)d_in[0];
    const int*   src = (const int*)d_in[1];
    const float* W   = (const float*)d_in[2];
    const float* b   = (const float*)d_in[3];
    float* out = (float*)d_out;

    k_init<<<(PERM_SIZE + 255) / 256, 256>>>();
    k_hist<<<256, 256>>>(src);
    k_scan<<<1, 32>>>();
    k_scatter<<<(N_ROWS + 255) / 256, 256>>>(src);
    k_gemm<<<MAX_TILES, NTHREADS>>>(x, W, b, out);
}

// round 3
// speedup vs baseline: 2.4130x; 2.4130x over previous
#include <cuda_runtime.h>
#include <cuda_bf16.h>
#include <cstdint>

// ---------------- problem constants ----------------
#define N_ROWS 131072
#define F_IN   256
#define N_SRC  32
#define F_OUT  64
#define W_COLS (N_SRC * F_OUT)   // 2048

#define BM 128
#define BK 64
#define CHUNKS (F_IN / BK)       // 4
#define NTHREADS 128             // 4 warps; each warp: 32 rows x 64 cols
#define PERM_SIZE (N_ROWS + N_SRC * BM)
#define MAX_TILES (N_ROWS / BM + N_SRC)    // 1056

// smem strides (bf16 elements); 72 -> 144B rows, 16B aligned, conflict-free
#define STRIDE 72
#define A_BYTES (BM * STRIDE * 2)      // 18432
#define B_BYTES (F_OUT * STRIDE * 2)   // 9216

#define SM_PERM 0                       // 128 * 4 = 512
#define SM_AHI  512
#define SM_ALO  (SM_AHI + A_BYTES)      // 18944
#define SM_BHI  (SM_ALO + A_BYTES)      // 37376
#define SM_BLO  (SM_BHI + B_BYTES)      // 46592
#define SM_TOTAL (SM_BLO + B_BYTES)     // 55808

// ---------------- device scratch (no cudaMalloc allowed) ----------------
__device__ int g_counts[N_SRC];
__device__ int g_off[N_SRC + 1];
__device__ int g_cursor[N_SRC * 32];               // 128B-padded counters
__device__ int g_perm[PERM_SIZE];
// W images: [src][n][k], k contiguous (256 per n). 1MB each.
__device__ __nv_bfloat16 g_Whi[N_SRC * F_OUT * F_IN];
__device__ __nv_bfloat16 g_Wlo[N_SRC * F_OUT * F_IN];

// ---------------- pass 0: reset ----------------
__global__ void k_init() {
    int i = blockIdx.x * blockDim.x + threadIdx.x;
    if (i < PERM_SIZE) g_perm[i] = -1;
    if (i < N_SRC) g_counts[i] = 0;
}

// ---------------- pass 1: histogram ----------------
__global__ void k_hist(const int* __restrict__ src) {
    __shared__ int bins[N_SRC];
    if (threadIdx.x < N_SRC) bins[threadIdx.x] = 0;
    __syncthreads();
    for (int i = blockIdx.x * blockDim.x + threadIdx.x; i < N_ROWS;
         i += gridDim.x * blockDim.x)
        atomicAdd(&bins[src[i]], 1);
    __syncthreads();
    if (threadIdx.x < N_SRC) atomicAdd(&g_counts[threadIdx.x], bins[threadIdx.x]);
}

// ---------------- pass 2: padded scan ----------------
__global__ void k_scan() {
    if (threadIdx.x == 0) {
        int acc = 0;
        for (int s = 0; s < N_SRC; s++) {
            g_off[s] = acc;
            g_cursor[s * 32] = acc;
            acc += ((g_counts[s] + BM - 1) / BM) * BM;
        }
        g_off[N_SRC] = acc;
    }
}

// ---------------- pass 3: scatter (warp-aggregated atomics) ----------------
__global__ void k_scatter(const int* __restrict__ src) {
    int i = blockIdx.x * blockDim.x + threadIdx.x;
    int s = src[i];
    unsigned m = __match_any_sync(0xffffffffu, s);
    int lane = threadIdx.x & 31;
    int leader = __ffs(m) - 1;
    int rank = __popc(m & ((1u << lane) - 1));
    int base = 0;
    if (lane == leader) base = atomicAdd(&g_cursor[s * 32], __popc(m));
    base = __shfl_sync(0xffffffffu, base, leader);
    g_perm[base + rank] = i;
}

// ---------------- pass 4: W -> [src][n][k] bf16 hi/lo (smem transpose) ----------------
// grid = 32 src x 4 kchunks; 256 threads
__global__ void k_prepW(const float* __restrict__ W) {
    __shared__ float tile[64][65];
    const int s = blockIdx.x >> 2;
    const int c = blockIdx.x & 3;
    const int tid = threadIdx.x;
    #pragma unroll
    for (int q = 0; q < 16; q++) {
        int idx = q * 256 + tid;
        int kk = idx >> 6, n = idx & 63;
        tile[kk][n] = W[(size_t)(c * 64 + kk) * W_COLS + s * F_OUT + n];
    }
    __syncthreads();
    #pragma unroll
    for (int q = 0; q < 16; q++) {
        int idx = q * 256 + tid;
        int n = idx >> 6, kk = idx & 63;
        float v = tile[kk][n];
        __nv_bfloat16 hi = __float2bfloat16(v);
        __nv_bfloat16 lo = __float2bfloat16(v - __bfloat162float(hi));
        size_t o = (size_t)(s * F_OUT + n) * F_IN + c * 64 + kk;
        g_Whi[o] = hi;
        g_Wlo[o] = lo;
    }
}

// ---------------- mma wrapper ----------------
__device__ __forceinline__ void mma_bf16(float* c, const uint32_t* a,
                                         uint32_t b0, uint32_t b1) {
    asm volatile(
        "mma.sync.aligned.m16n8k16.row.col.f32.bf16.bf16.f32 "
        "{%0,%1,%2,%3}, {%4,%5,%6,%7}, {%8,%9}, {%0,%1,%2,%3};"
        : "+f"(c[0]), "+f"(c[1]), "+f"(c[2]), "+f"(c[3])
        : "r"(a[0]), "r"(a[1]), "r"(a[2]), "r"(a[3]), "r"(b0), "r"(b1));
}

// ---------------- pass 5: HMMA GEMM ----------------
__global__ void __launch_bounds__(NTHREADS)
k_gemm(const float* __restrict__ x, const float* __restrict__ b,
       float* __restrict__ out) {
    extern __shared__ char smem[];
    const int tid = threadIdx.x;
    const int wid = tid >> 5;
    const int lid = tid & 31;
    const int g4 = lid >> 2;       // 0..7  (row group within fragment)
    const int q4 = lid & 3;        // 0..3  (k-pair within fragment)
    const int tstart = blockIdx.x * BM;

    // tile -> source
    __shared__ int s_src;
    if (tid == 0) {
        int srcid = -1;
        if (tstart < g_off[N_SRC]) {
            for (int s = 0; s < N_SRC; s++)
                if (tstart >= g_off[s] && tstart < g_off[s + 1]) { srcid = s; break; }
        }
        s_src = srcid;
    }
    __syncthreads();
    const int src = s_src;
    if (src < 0) return;

    int* sperm = (int*)(smem + SM_PERM);
    sperm[tid] = g_perm[tstart + tid];   // 128 threads, 128 entries
    __syncthreads();

    char* const Ahi = smem + SM_AHI;
    char* const Alo = smem + SM_ALO;
    char* const Bhi = smem + SM_BHI;
    char* const Blo = smem + SM_BLO;

    float acc[2][8][4];
    #pragma unroll
    for (int mb = 0; mb < 2; mb++)
        #pragma unroll
        for (int nb = 0; nb < 8; nb++)
            #pragma unroll
            for (int j = 0; j < 4; j++) acc[mb][nb][j] = 0.0f;

    const int myrow = tid >> 4;          // for A staging: rows 2 per 32 lanes? no: below
    (void)myrow;

    #pragma unroll 1
    for (int c = 0; c < CHUNKS; c++) {
        if (c > 0) __syncthreads();   // protect smem reuse

        // --- stage A: 128 rows x 64 k; 2048 float4, 16 per thread ---
        #pragma unroll
        for (int q = 0; q < 16; q++) {
            int i = q * NTHREADS + tid;
            int row = i >> 4;
            int seg = i & 15;             // float4 index within 64 k
            int prow = sperm[row];
            float4 v = make_float4(0.f, 0.f, 0.f, 0.f);
            if (prow >= 0)
                v = __ldg((const float4*)(x + (size_t)prow * F_IN + c * BK + seg * 4));
            __nv_bfloat162 h01 = __floats2bfloat162_rn(v.x, v.y);
            __nv_bfloat162 h23 = __floats2bfloat162_rn(v.z, v.w);
            float lx = v.x - __bfloat162float(h01.x);
            float ly = v.y - __bfloat162float(h01.y);
            float lz = v.z - __bfloat162float(h23.x);
            float lw = v.w - __bfloat162float(h23.y);
            __nv_bfloat162 l01 = __floats2bfloat162_rn(lx, ly);
            __nv_bfloat162 l23 = __floats2bfloat162_rn(lz, lw);
            uint32_t off = row * (STRIDE * 2) + seg * 8;
            *(uint2*)(Ahi + off) = make_uint2(*(uint32_t*)&h01, *(uint32_t*)&h23);
            *(uint2*)(Alo + off) = make_uint2(*(uint32_t*)&l01, *(uint32_t*)&l23);
        }

        // --- stage B: 64 n x 64 k; 512 uint4 per split, 4 per thread ---
        #pragma unroll
        for (int q = 0; q < 4; q++) {
            int i = q * NTHREADS + tid;
            int n = i >> 3;
            int k8 = i & 7;               // 8 bf16 per uint4
            size_t go = ((size_t)(src * F_OUT + n) * F_IN + c * 64 + k8 * 8);
            uint32_t so = n * (STRIDE * 2) + k8 * 16;
            *(uint4*)(Bhi + so) = *(const uint4*)(g_Whi + go);
            *(uint4*)(Blo + so) = *(const uint4*)(g_Wlo + go);
        }
        __syncthreads();

        // --- compute: 3 split terms x 4 k-steps of 16 ---
        #pragma unroll
        for (int t = 0; t < 3; t++) {
            const char* A = (t == 2) ? Alo : Ahi;
            const char* B = (t == 1) ? Blo : Bhi;
            #pragma unroll
            for (int ks = 0; ks < 4; ks++) {
                const int kb = ks * 32;               // 16 bf16 = 32 bytes
                uint32_t a[2][4];
                #pragma unroll
                for (int mb = 0; mb < 2; mb++) {
                    int r0 = wid * 32 + mb * 16 + g4;
                    const char* base = A + r0 * (STRIDE * 2) + kb + q4 * 4;
                    a[mb][0] = *(const uint32_t*)(base);
                    a[mb][1] = *(const uint32_t*)(base + 8 * (STRIDE * 2));
                    a[mb][2] = *(const uint32_t*)(base + 16);
                    a[mb][3] = *(const uint32_t*)(base + 8 * (STRIDE * 2) + 16);
                }
                #pragma unroll
                for (int nb = 0; nb < 8; nb++) {
                    int n0 = nb * 8 + g4;
                    const char* bp = B + n0 * (STRIDE * 2) + kb + q4 * 4;
                    uint32_t b0 = *(const uint32_t*)(bp);
                    uint32_t b1 = *(const uint32_t*)(bp + 16);
                    mma_bf16(acc[0][nb], a[0], b0, b1);
                    mma_bf16(acc[1][nb], a[1], b0, b1);
                }
            }
        }
    }

    // --- epilogue: bias + store ---
    #pragma unroll
    for (int nb = 0; nb < 8; nb++) {
        int col = nb * 8 + q4 * 2;
        float2 bv = *(const float2*)(b + src * F_OUT + col);
        #pragma unroll
        for (int mb = 0; mb < 2; mb++) {
            #pragma unroll
            for (int half = 0; half < 2; half++) {
                int r = wid * 32 + mb * 16 + g4 + half * 8;
                int prow = sperm[r];
                if (prow >= 0) {
                    float2 o;
                    o.x = acc[mb][nb][half * 2 + 0] + bv.x;
                    o.y = acc[mb][nb][half * 2 + 1] + bv.y;
                    *(float2*)(out + (size_t)prow * F_OUT + col) = o;
                }
            }
        }
    }
}

// ---------------- launch ----------------
extern "C" void kernel_launch(void* const* d_in, const int* in_sizes, int n_in,
                              void* d_out, int out_size) {
    const float* x   = (const float*)d_in[0];
    const int*   src = (const int*)d_in[1];
    const float* W   = (const float*)d_in[2];
    const float* b   = (const float*)d_in[3];
    float* out = (float*)d_out;

    static int smem_set = 0;
    if (!smem_set) {
        cudaFuncSetAttribute(k_gemm, cudaFuncAttributeMaxDynamicSharedMemorySize, SM_TOTAL);
        smem_set = 1;
    }

    k_init<<<(PERM_SIZE + 255) / 256, 256>>>();
    k_hist<<<512, 256>>>(src);
    k_scan<<<1, 32>>>();
    k_scatter<<<N_ROWS / 256, 256>>>(src);
    k_prepW<<<N_SRC * CHUNKS, 256>>>(W);
    k_gemm<<<MAX_TILES, NTHREADS, SM_TOTAL>>>(x, b, out);
}

// round 4
// speedup vs baseline: 3.2308x; 1.3389x over previous
#include <cuda_runtime.h>
#include <cuda_bf16.h>
#include <cstdint>

// ---------------- problem constants ----------------
#define N_ROWS 131072
#define F_IN   256
#define N_SRC  32
#define F_OUT  64
#define W_COLS (N_SRC * F_OUT)   // 2048

#define BM 128
#define BK 64
#define CHUNKS (F_IN / BK)       // 4
#define NTHREADS 128
#define CAP 8192                 // per-source bucket capacity (max count ~4400 w.h.p.)
#define TILES_PER_SRC (CAP / BM) // 64
#define GRID_GEMM (N_SRC * TILES_PER_SRC)  // 2048

// smem strides (bf16 elements); 72 -> 144B rows, conflict-free for ldmatrix
#define STRIDE 72
#define SB (STRIDE * 2)                // 144 bytes per row
#define A_BYTES (BM * SB)              // 18432
#define B_BYTES (F_OUT * SB)           // 9216

#define SM_PERM 0
#define SM_AHI  512
#define SM_ALO  (SM_AHI + A_BYTES)
#define SM_BHI  (SM_ALO + A_BYTES)
#define SM_BLO  (SM_BHI + B_BYTES)
#define SM_TOTAL (SM_BLO + B_BYTES)    // 55808

// ---------------- device scratch ----------------
__device__ int g_cursor[N_SRC * 32];               // 128B-padded cursors
__device__ int g_perm[N_SRC * CAP];                // bucketed permutation
__device__ __nv_bfloat16 g_Whi[N_SRC * F_OUT * F_IN];  // [src][n][k]
__device__ __nv_bfloat16 g_Wlo[N_SRC * F_OUT * F_IN];

// ---------------- pass 0: reset (perm -1, cursors to bucket bases) ----------------
__global__ void k_init() {
    int i = blockIdx.x * blockDim.x + threadIdx.x;
    int4* p4 = (int4*)g_perm;
    p4[i] = make_int4(-1, -1, -1, -1);             // covers N_SRC*CAP ints
    if (i < N_SRC) g_cursor[i * 32] = i * CAP;
}

// ---------------- pass 1: scatter (warp-aggregated, ILP=4) ----------------
__global__ void k_scatter(const int* __restrict__ src) {
    int i0 = (blockIdx.x * blockDim.x + threadIdx.x) * 4;
    int4 s4 = *(const int4*)(src + i0);
    int sv[4] = { s4.x, s4.y, s4.z, s4.w };
    int lane = threadIdx.x & 31;
    #pragma unroll
    for (int j = 0; j < 4; j++) {
        int s = sv[j];
        unsigned m = __match_any_sync(0xffffffffu, s);
        int leader = __ffs(m) - 1;
        int rank = __popc(m & ((1u << lane) - 1));
        int base = 0;
        if (lane == leader) base = atomicAdd(&g_cursor[s * 32], __popc(m));
        base = __shfl_sync(0xffffffffu, base, leader);
        g_perm[base + rank] = i0 + j;
    }
}

// ---------------- pass 2: W -> [src][n][k] bf16 hi/lo (smem transpose) ----------------
__global__ void k_prepW(const float* __restrict__ W) {
    __shared__ float tile[64][65];
    const int s = blockIdx.x >> 2;
    const int c = blockIdx.x & 3;
    const int tid = threadIdx.x;
    #pragma unroll
    for (int q = 0; q < 16; q++) {
        int idx = q * 256 + tid;
        int kk = idx >> 6, n = idx & 63;
        tile[kk][n] = W[(size_t)(c * 64 + kk) * W_COLS + s * F_OUT + n];
    }
    __syncthreads();
    #pragma unroll
    for (int q = 0; q < 16; q++) {
        int idx = q * 256 + tid;
        int n = idx >> 6, kk = idx & 63;
        float v = tile[kk][n];
        __nv_bfloat16 hi = __float2bfloat16(v);
        __nv_bfloat16 lo = __float2bfloat16(v - __bfloat162float(hi));
        size_t o = (size_t)(s * F_OUT + n) * F_IN + c * 64 + kk;
        g_Whi[o] = hi;
        g_Wlo[o] = lo;
    }
}

// ---------------- wrappers ----------------
__device__ __forceinline__ void mma_bf16(float* c, const uint32_t* a,
                                         uint32_t b0, uint32_t b1) {
    asm volatile(
        "mma.sync.aligned.m16n8k16.row.col.f32.bf16.bf16.f32 "
        "{%0,%1,%2,%3}, {%4,%5,%6,%7}, {%8,%9}, {%0,%1,%2,%3};"
        : "+f"(c[0]), "+f"(c[1]), "+f"(c[2]), "+f"(c[3])
        : "r"(a[0]), "r"(a[1]), "r"(a[2]), "r"(a[3]), "r"(b0), "r"(b1));
}
__device__ __forceinline__ void ldm_x4(uint32_t* r, uint32_t addr) {
    asm volatile("ldmatrix.sync.aligned.m8n8.x4.shared.b16 {%0,%1,%2,%3}, [%4];"
        : "=r"(r[0]), "=r"(r[1]), "=r"(r[2]), "=r"(r[3]) : "r"(addr));
}

// ---------------- pass 3: HMMA GEMM ----------------
__global__ void __launch_bounds__(NTHREADS, 4)
k_gemm(const float* __restrict__ x, const float* __restrict__ b,
       float* __restrict__ out) {
    extern __shared__ char smem[];
    const int tid = threadIdx.x;
    const int wid = tid >> 5;
    const int lid = tid & 31;
    const int g4 = lid >> 2;
    const int q4 = lid & 3;

    const int src   = blockIdx.x >> 6;
    const int local = blockIdx.x & (TILES_PER_SRC - 1);
    const int count = g_cursor[src * 32] - src * CAP;
    if (local * BM >= count) return;

    int* sperm = (int*)(smem + SM_PERM);
    sperm[tid] = g_perm[src * CAP + local * BM + tid];
    __syncthreads();

    char* const Ahi = smem + SM_AHI;
    char* const Alo = smem + SM_ALO;
    char* const Bhi = smem + SM_BHI;
    char* const Blo = smem + SM_BLO;

    const uint32_t aHiB = (uint32_t)__cvta_generic_to_shared(Ahi);
    const uint32_t aLoB = (uint32_t)__cvta_generic_to_shared(Alo);
    const uint32_t bHiB = (uint32_t)__cvta_generic_to_shared(Bhi);
    const uint32_t bLoB = (uint32_t)__cvta_generic_to_shared(Blo);

    // ldmatrix lane offsets (bytes)
    const uint32_t offA = ((lid & 7) + ((lid >> 3) & 1) * 8) * SB + ((lid >> 4) & 1) * 16;
    const uint32_t offB = ((lid & 7) + ((lid >> 4) & 1) * 8) * SB + ((lid >> 3) & 1) * 16;

    float acc[2][8][4];
    #pragma unroll
    for (int mb = 0; mb < 2; mb++)
        #pragma unroll
        for (int nb = 0; nb < 8; nb++)
            #pragma unroll
            for (int j = 0; j < 4; j++) acc[mb][nb][j] = 0.0f;

    #pragma unroll 1
    for (int c = 0; c < CHUNKS; c++) {
        if (c > 0) __syncthreads();

        // stage A: 128 rows x 64 k; 16 float4 per thread, fp32 -> bf16 hi/lo
        #pragma unroll
        for (int q = 0; q < 16; q++) {
            int i = q * NTHREADS + tid;
            int row = i >> 4;
            int seg = i & 15;
            int prow = sperm[row];
            float4 v = make_float4(0.f, 0.f, 0.f, 0.f);
            if (prow >= 0)
                v = __ldg((const float4*)(x + (size_t)prow * F_IN + c * BK + seg * 4));
            __nv_bfloat162 h01 = __floats2bfloat162_rn(v.x, v.y);
            __nv_bfloat162 h23 = __floats2bfloat162_rn(v.z, v.w);
            __nv_bfloat162 l01 = __floats2bfloat162_rn(v.x - __bfloat162float(h01.x),
                                                       v.y - __bfloat162float(h01.y));
            __nv_bfloat162 l23 = __floats2bfloat162_rn(v.z - __bfloat162float(h23.x),
                                                       v.w - __bfloat162float(h23.y));
            uint32_t off = row * SB + seg * 8;
            *(uint2*)(Ahi + off) = make_uint2(*(uint32_t*)&h01, *(uint32_t*)&h23);
            *(uint2*)(Alo + off) = make_uint2(*(uint32_t*)&l01, *(uint32_t*)&l23);
        }
        // stage B: 64 n x 64 k; 4 uint4 per thread per split
        #pragma unroll
        for (int q = 0; q < 4; q++) {
            int i = q * NTHREADS + tid;
            int n = i >> 3;
            int k8 = i & 7;
            size_t go = ((size_t)(src * F_OUT + n) * F_IN + c * 64 + k8 * 8);
            uint32_t so = n * SB + k8 * 16;
            *(uint4*)(Bhi + so) = *(const uint4*)(g_Whi + go);
            *(uint4*)(Blo + so) = *(const uint4*)(g_Wlo + go);
        }
        __syncthreads();

        // compute: fragments loaded ONCE per k-step, reused across 3 split terms
        #pragma unroll
        for (int ks = 0; ks < 4; ks++) {
            uint32_t ahi[2][4], alo[2][4];
            #pragma unroll
            for (int mb = 0; mb < 2; mb++) {
                uint32_t rowoff = (uint32_t)(wid * 32 + mb * 16) * SB + ks * 32;
                ldm_x4(ahi[mb], aHiB + rowoff + offA);
                ldm_x4(alo[mb], aLoB + rowoff + offA);
            }
            #pragma unroll
            for (int p = 0; p < 4; p++) {
                uint32_t bo = (uint32_t)(p * 16) * SB + ks * 32 + offB;
                uint32_t bhi[4], blo[4];
                ldm_x4(bhi, bHiB + bo);
                ldm_x4(blo, bLoB + bo);
                #pragma unroll
                for (int mb = 0; mb < 2; mb++) {
                    mma_bf16(acc[mb][p * 2 + 0], ahi[mb], bhi[0], bhi[1]);
                    mma_bf16(acc[mb][p * 2 + 1], ahi[mb], bhi[2], bhi[3]);
                    mma_bf16(acc[mb][p * 2 + 0], ahi[mb], blo[0], blo[1]);
                    mma_bf16(acc[mb][p * 2 + 1], ahi[mb], blo[2], blo[3]);
                    mma_bf16(acc[mb][p * 2 + 0], alo[mb], bhi[0], bhi[1]);
                    mma_bf16(acc[mb][p * 2 + 1], alo[mb], bhi[2], bhi[3]);
                }
            }
        }
    }

    // epilogue: bias + scattered store
    #pragma unroll
    for (int nb = 0; nb < 8; nb++) {
        int col = nb * 8 + q4 * 2;
        float2 bv = *(const float2*)(b + src * F_OUT + col);
        #pragma unroll
        for (int mb = 0; mb < 2; mb++) {
            #pragma unroll
            for (int half = 0; half < 2; half++) {
                int r = wid * 32 + mb * 16 + g4 + half * 8;
                int prow = sperm[r];
                if (prow >= 0) {
                    float2 o;
                    o.x = acc[mb][nb][half * 2 + 0] + bv.x;
                    o.y = acc[mb][nb][half * 2 + 1] + bv.y;
                    *(float2*)(out + (size_t)prow * F_OUT + col) = o;
                }
            }
        }
    }
}

// ---------------- launch ----------------
extern "C" void kernel_launch(void* const* d_in, const int* in_sizes, int n_in,
                              void* d_out, int out_size) {
    const float* x   = (const float*)d_in[0];
    const int*   src = (const int*)d_in[1];
    const float* W   = (const float*)d_in[2];
    const float* b   = (const float*)d_in[3];
    float* out = (float*)d_out;

    cudaFuncSetAttribute(k_gemm, cudaFuncAttributeMaxDynamicSharedMemorySize, SM_TOTAL);

    k_init<<<(N_SRC * CAP / 4) / 256, 256>>>();
    k_scatter<<<N_ROWS / (256 * 4), 256>>>(src);
    k_prepW<<<N_SRC * CHUNKS, 256>>>(W);
    k_gemm<<<GRID_GEMM, NTHREADS, SM_TOTAL>>>(x, b, out);
}

// round 5
// speedup vs baseline: 3.2946x; 1.0197x over previous
#include <cuda_runtime.h>
#include <cuda_bf16.h>
#include <cstdint>

// ---------------- problem constants ----------------
#define N_ROWS 131072
#define F_IN   256
#define N_SRC  32
#define F_OUT  64
#define W_COLS (N_SRC * F_OUT)   // 2048

#define BM 128
#define BK 64
#define CHUNKS (F_IN / BK)       // 4
#define NTHREADS 128
#define CAP 8192
#define TILES_PER_SRC (CAP / BM) // 64
#define GRID_GEMM (N_SRC * TILES_PER_SRC)  // 2048

// smem: 144B rows (72 bf16) -> conflict-free ldmatrix, 16B-aligned cp.async dst
#define SB 144
#define A_BYTES (BM * SB)              // 18432
#define B_BYTES (F_OUT * SB)           // 9216
#define STAGE_BYTES (2 * A_BYTES + 2 * B_BYTES)  // 55296
#define OFF_AHI 0
#define OFF_ALO A_BYTES
#define OFF_BHI (2 * A_BYTES)
#define OFF_BLO (2 * A_BYTES + B_BYTES)
#define SM_PERM 0
#define SM_STAGE 512
#define SM_TOTAL (SM_STAGE + 2 * STAGE_BYTES)    // 111104

// ---------------- device scratch ----------------
__device__ int g_cursor[N_SRC * 32];
__device__ int g_perm[N_SRC * CAP];
__device__ __nv_bfloat16 g_Whi[N_SRC * F_OUT * F_IN];  // [src][n][k]
__device__ __nv_bfloat16 g_Wlo[N_SRC * F_OUT * F_IN];
__device__ __nv_bfloat16 g_xhi[(size_t)N_ROWS * F_IN]; // [row][k] 64MB
__device__ __nv_bfloat16 g_xlo[(size_t)N_ROWS * F_IN]; // 64MB

// ---------------- pass 0: reset ----------------
__global__ void k_init() {
    int i = blockIdx.x * blockDim.x + threadIdx.x;
    ((int4*)g_perm)[i] = make_int4(-1, -1, -1, -1);
    if (i < N_SRC) g_cursor[i * 32] = i * CAP;
}

// ---------------- pass 1: scatter (warp-aggregated, ILP=4) ----------------
__global__ void k_scatter(const int* __restrict__ src) {
    int i0 = (blockIdx.x * blockDim.x + threadIdx.x) * 4;
    int4 s4 = *(const int4*)(src + i0);
    int sv[4] = { s4.x, s4.y, s4.z, s4.w };
    int lane = threadIdx.x & 31;
    #pragma unroll
    for (int j = 0; j < 4; j++) {
        int s = sv[j];
        unsigned m = __match_any_sync(0xffffffffu, s);
        int leader = __ffs(m) - 1;
        int rank = __popc(m & ((1u << lane) - 1));
        int base = 0;
        if (lane == leader) base = atomicAdd(&g_cursor[s * 32], __popc(m));
        base = __shfl_sync(0xffffffffu, base, leader);
        g_perm[base + rank] = i0 + j;
    }
}

// ---------------- pass 2: W -> [src][n][k] bf16 hi/lo ----------------
__global__ void k_prepW(const float* __restrict__ W) {
    __shared__ float tile[64][65];
    const int s = blockIdx.x >> 2;
    const int c = blockIdx.x & 3;
    const int tid = threadIdx.x;
    #pragma unroll
    for (int q = 0; q < 16; q++) {
        int idx = q * 256 + tid;
        int kk = idx >> 6, n = idx & 63;
        tile[kk][n] = W[(size_t)(c * 64 + kk) * W_COLS + s * F_OUT + n];
    }
    __syncthreads();
    #pragma unroll
    for (int q = 0; q < 16; q++) {
        int idx = q * 256 + tid;
        int n = idx >> 6, kk = idx & 63;
        float v = tile[kk][n];
        __nv_bfloat16 hi = __float2bfloat16(v);
        __nv_bfloat16 lo = __float2bfloat16(v - __bfloat162float(hi));
        size_t o = (size_t)(s * F_OUT + n) * F_IN + c * 64 + kk;
        g_Whi[o] = hi;
        g_Wlo[o] = lo;
    }
}

// ---------------- pass 3: x -> bf16 hi/lo images (pure streaming) ----------------
__global__ void k_prepX(const float* __restrict__ x) {
    size_t i = (size_t)blockIdx.x * blockDim.x + threadIdx.x;  // one float4 each
    float4 v = __ldg((const float4*)x + i);
    __nv_bfloat162 h01 = __floats2bfloat162_rn(v.x, v.y);
    __nv_bfloat162 h23 = __floats2bfloat162_rn(v.z, v.w);
    __nv_bfloat162 l01 = __floats2bfloat162_rn(v.x - __bfloat162float(h01.x),
                                               v.y - __bfloat162float(h01.y));
    __nv_bfloat162 l23 = __floats2bfloat162_rn(v.z - __bfloat162float(h23.x),
                                               v.w - __bfloat162float(h23.y));
    ((uint2*)g_xhi)[i] = make_uint2(*(uint32_t*)&h01, *(uint32_t*)&h23);
    ((uint2*)g_xlo)[i] = make_uint2(*(uint32_t*)&l01, *(uint32_t*)&l23);
}

// ---------------- wrappers ----------------
__device__ __forceinline__ void mma_bf16(float* c, const uint32_t* a,
                                         uint32_t b0, uint32_t b1) {
    asm volatile(
        "mma.sync.aligned.m16n8k16.row.col.f32.bf16.bf16.f32 "
        "{%0,%1,%2,%3}, {%4,%5,%6,%7}, {%8,%9}, {%0,%1,%2,%3};"
        : "+f"(c[0]), "+f"(c[1]), "+f"(c[2]), "+f"(c[3])
        : "r"(a[0]), "r"(a[1]), "r"(a[2]), "r"(a[3]), "r"(b0), "r"(b1));
}
__device__ __forceinline__ void ldm_x4(uint32_t* r, uint32_t addr) {
    asm volatile("ldmatrix.sync.aligned.m8n8.x4.shared.b16 {%0,%1,%2,%3}, [%4];"
        : "=r"(r[0]), "=r"(r[1]), "=r"(r[2]), "=r"(r[3]) : "r"(addr));
}
__device__ __forceinline__ void cpa16(uint32_t dst, const void* src, int srcsz) {
    asm volatile("cp.async.ca.shared.global [%0], [%1], 16, %2;"
        :: "r"(dst), "l"(src), "r"(srcsz) : "memory");
}
__device__ __forceinline__ void cpa_commit() {
    asm volatile("cp.async.commit_group;" ::: "memory");
}

// ---------------- pass 4: cp.async double-buffered HMMA GEMM ----------------
__global__ void __launch_bounds__(NTHREADS, 2)
k_gemm(const float* __restrict__ b, float* __restrict__ out) {
    extern __shared__ char smem[];
    const int tid = threadIdx.x;
    const int wid = tid >> 5;
    const int lid = tid & 31;
    const int g4 = lid >> 2;
    const int q4 = lid & 3;

    const int src   = blockIdx.x >> 6;
    const int local = blockIdx.x & (TILES_PER_SRC - 1);
    const int count = g_cursor[src * 32] - src * CAP;
    if (local * BM >= count) return;

    int* sperm = (int*)(smem + SM_PERM);
    sperm[tid] = g_perm[src * CAP + local * BM + tid];
    __syncthreads();

    const uint32_t smb = (uint32_t)__cvta_generic_to_shared(smem);
    const uint32_t stage0 = smb + SM_STAGE;

    // chunk-invariant staging indices
    int prow_a[8];      // A rows this thread stages: row = tid>>3 + 16*q
    #pragma unroll
    for (int q = 0; q < 8; q++) prow_a[q] = sperm[(tid >> 3) + 16 * q];
    const int ga = tid & 7;                 // A granule within row
    const int arow0 = tid >> 3;

    // ldmatrix lane offsets (bytes)
    const uint32_t offA = ((lid & 7) + ((lid >> 3) & 1) * 8) * SB + ((lid >> 4) & 1) * 16;
    const uint32_t offB = ((lid & 7) + ((lid >> 4) & 1) * 8) * SB + ((lid >> 3) & 1) * 16;

    float acc[2][8][4];
    #pragma unroll
    for (int mb = 0; mb < 2; mb++)
        #pragma unroll
        for (int nb = 0; nb < 8; nb++)
            #pragma unroll
            for (int j = 0; j < 4; j++) acc[mb][nb][j] = 0.0f;

    // ---- stage issuer: chunk c into buffer buf ----
    auto issue = [&](int c, int buf) {
        const uint32_t bs = stage0 + buf * STAGE_BYTES;
        // A: 8 rows/thread, granule ga; hi & lo
        #pragma unroll
        for (int q = 0; q < 8; q++) {
            int row = arow0 + 16 * q;
            int prow = prow_a[q];
            int sz = (prow >= 0) ? 16 : 0;
            size_t gb = ((size_t)(prow >= 0 ? prow : 0) * F_IN + c * BK) * 2 + ga * 16;
            uint32_t dst = bs + row * SB + ga * 16;
            cpa16(dst + OFF_AHI, (const char*)g_xhi + gb, sz);
            cpa16(dst + OFF_ALO, (const char*)g_xlo + gb, sz);
        }
        // B: 512 granules per split / 128 thr = 4 each
        #pragma unroll
        for (int q = 0; q < 4; q++) {
            int i = q * NTHREADS + tid;
            int n = i >> 3, g = i & 7;
            size_t gb = ((size_t)(src * F_OUT + n) * F_IN + c * BK) * 2 + g * 16;
            uint32_t dst = bs + n * SB + g * 16;
            cpa16(dst + OFF_BHI, (const char*)g_Whi + gb, 16);
            cpa16(dst + OFF_BLO, (const char*)g_Wlo + gb, 16);
        }
        cpa_commit();
    };

    issue(0, 0);

    #pragma unroll
    for (int c = 0; c < CHUNKS; c++) {
        if (c + 1 < CHUNKS) {
            issue(c + 1, (c + 1) & 1);
            asm volatile("cp.async.wait_group 1;" ::: "memory");
        } else {
            asm volatile("cp.async.wait_group 0;" ::: "memory");
        }
        __syncthreads();

        const uint32_t bs = stage0 + (c & 1) * STAGE_BYTES;
        const uint32_t aHiB = bs + OFF_AHI, aLoB = bs + OFF_ALO;
        const uint32_t bHiB = bs + OFF_BHI, bLoB = bs + OFF_BLO;

        #pragma unroll
        for (int ks = 0; ks < 4; ks++) {
            uint32_t ahi[2][4], alo[2][4];
            #pragma unroll
            for (int mb = 0; mb < 2; mb++) {
                uint32_t rowoff = (uint32_t)(wid * 32 + mb * 16) * SB + ks * 32;
                ldm_x4(ahi[mb], aHiB + rowoff + offA);
                ldm_x4(alo[mb], aLoB + rowoff + offA);
            }
            #pragma unroll
            for (int p = 0; p < 4; p++) {
                uint32_t bo = (uint32_t)(p * 16) * SB + ks * 32 + offB;
                uint32_t bhi[4], blo[4];
                ldm_x4(bhi, bHiB + bo);
                ldm_x4(blo, bLoB + bo);
                #pragma unroll
                for (int mb = 0; mb < 2; mb++) {
                    mma_bf16(acc[mb][p * 2 + 0], ahi[mb], bhi[0], bhi[1]);
                    mma_bf16(acc[mb][p * 2 + 1], ahi[mb], bhi[2], bhi[3]);
                    mma_bf16(acc[mb][p * 2 + 0], ahi[mb], blo[0], blo[1]);
                    mma_bf16(acc[mb][p * 2 + 1], ahi[mb], blo[2], blo[3]);
                    mma_bf16(acc[mb][p * 2 + 0], alo[mb], bhi[0], bhi[1]);
                    mma_bf16(acc[mb][p * 2 + 1], alo[mb], bhi[2], bhi[3]);
                }
            }
        }
        __syncthreads();
    }

    // epilogue: bias + scattered store
    #pragma unroll
    for (int nb = 0; nb < 8; nb++) {
        int col = nb * 8 + q4 * 2;
        float2 bv = *(const float2*)(b + src * F_OUT + col);
        #pragma unroll
        for (int mb = 0; mb < 2; mb++) {
            #pragma unroll
            for (int half = 0; half < 2; half++) {
                int r = wid * 32 + mb * 16 + g4 + half * 8;
                int prow = sperm[r];
                if (prow >= 0) {
                    float2 o;
                    o.x = acc[mb][nb][half * 2 + 0] + bv.x;
                    o.y = acc[mb][nb][half * 2 + 1] + bv.y;
                    *(float2*)(out + (size_t)prow * F_OUT + col) = o;
                }
            }
        }
    }
}

// ---------------- launch ----------------
extern "C" void kernel_launch(void* const* d_in, const int* in_sizes, int n_in,
                              void* d_out, int out_size) {
    const float* x   = (const float*)d_in[0];
    const int*   src = (const int*)d_in[1];
    const float* W   = (const float*)d_in[2];
    const float* b   = (const float*)d_in[3];
    float* out = (float*)d_out;

    cudaFuncSetAttribute(k_gemm, cudaFuncAttributeMaxDynamicSharedMemorySize, SM_TOTAL);

    k_init<<<(N_SRC * CAP / 4) / 256, 256>>>();
    k_scatter<<<N_ROWS / (256 * 4), 256>>>(src);
    k_prepW<<<N_SRC * CHUNKS, 256>>>(W);
    k_prepX<<<(N_ROWS * (F_IN / 4)) / 256, 256>>>(x);
    k_gemm<<<GRID_GEMM, NTHREADS, SM_TOTAL>>>(b, out);
}

// round 6
// speedup vs baseline: 3.9721x; 1.2056x over previous
#include <cuda_runtime.h>
#include <cuda_bf16.h>
#include <cstdint>

// ---------------- problem constants ----------------
#define N_ROWS 131072
#define F_IN   256
#define N_SRC  32
#define F_OUT  64
#define W_COLS (N_SRC * F_OUT)   // 2048

#define BM 128
#define BK 64
#define CHUNKS (F_IN / BK)       // 4
#define NTHREADS 128
#define CAP 8192
#define TILES_PER_SRC (CAP / BM) // 64
#define GRID_GEMM (N_SRC * TILES_PER_SRC)  // 2048

// stage layout (per buffer):
//   A: 128 rows x 288B (64 fp32 + 8 pad floats)  -> conflict-free LDS.64 frags
//   Bhi/Blo: 64 rows x 144B bf16 (72 bf16)       -> conflict-free ldmatrix
#define ASB 288
#define SB  144
#define A_BYTES (BM * ASB)             // 36864
#define B_BYTES (F_OUT * SB)           // 9216
#define OFF_A   0
#define OFF_BHI A_BYTES
#define OFF_BLO (A_BYTES + B_BYTES)
#define STAGE_BYTES (A_BYTES + 2 * B_BYTES)   // 55296
#define SM_PERM 0
#define SM_STAGE 512
#define SM_TOTAL (SM_STAGE + 2 * STAGE_BYTES) // 111104

// ---------------- device scratch ----------------
__device__ int g_cursor[N_SRC * 32];
__device__ int g_perm[N_SRC * CAP];
__device__ __nv_bfloat16 g_Whi[N_SRC * F_OUT * F_IN];  // [src][n][k]
__device__ __nv_bfloat16 g_Wlo[N_SRC * F_OUT * F_IN];

// ---------------- pass 0: reset ----------------
__global__ void k_init() {
    int i = blockIdx.x * blockDim.x + threadIdx.x;
    ((int4*)g_perm)[i] = make_int4(-1, -1, -1, -1);
    if (i < N_SRC) g_cursor[i * 32] = i * CAP;
}

// ---------------- pass 1: scatter (warp-aggregated, ILP=4) ----------------
__global__ void k_scatter(const int* __restrict__ src) {
    int i0 = (blockIdx.x * blockDim.x + threadIdx.x) * 4;
    int4 s4 = *(const int4*)(src + i0);
    int sv[4] = { s4.x, s4.y, s4.z, s4.w };
    int lane = threadIdx.x & 31;
    #pragma unroll
    for (int j = 0; j < 4; j++) {
        int s = sv[j];
        unsigned m = __match_any_sync(0xffffffffu, s);
        int leader = __ffs(m) - 1;
        int rank = __popc(m & ((1u << lane) - 1));
        int base = 0;
        if (lane == leader) base = atomicAdd(&g_cursor[s * 32], __popc(m));
        base = __shfl_sync(0xffffffffu, base, leader);
        g_perm[base + rank] = i0 + j;
    }
}

// ---------------- pass 2: W -> [src][n][k] bf16 hi/lo ----------------
__global__ void k_prepW(const float* __restrict__ W) {
    __shared__ float tile[64][65];
    const int s = blockIdx.x >> 2;
    const int c = blockIdx.x & 3;
    const int tid = threadIdx.x;
    #pragma unroll
    for (int q = 0; q < 16; q++) {
        int idx = q * 256 + tid;
        int kk = idx >> 6, n = idx & 63;
        tile[kk][n] = W[(size_t)(c * 64 + kk) * W_COLS + s * F_OUT + n];
    }
    __syncthreads();
    #pragma unroll
    for (int q = 0; q < 16; q++) {
        int idx = q * 256 + tid;
        int n = idx >> 6, kk = idx & 63;
        float v = tile[kk][n];
        __nv_bfloat16 hi = __float2bfloat16(v);
        __nv_bfloat16 lo = __float2bfloat16(v - __bfloat162float(hi));
        size_t o = (size_t)(s * F_OUT + n) * F_IN + c * 64 + kk;
        g_Whi[o] = hi;
        g_Wlo[o] = lo;
    }
}

// ---------------- wrappers ----------------
__device__ __forceinline__ void mma_bf16(float* c, const uint32_t* a,
                                         uint32_t b0, uint32_t b1) {
    asm volatile(
        "mma.sync.aligned.m16n8k16.row.col.f32.bf16.bf16.f32 "
        "{%0,%1,%2,%3}, {%4,%5,%6,%7}, {%8,%9}, {%0,%1,%2,%3};"
        : "+f"(c[0]), "+f"(c[1]), "+f"(c[2]), "+f"(c[3])
        : "r"(a[0]), "r"(a[1]), "r"(a[2]), "r"(a[3]), "r"(b0), "r"(b1));
}
__device__ __forceinline__ void ldm_x4(uint32_t* r, uint32_t addr) {
    asm volatile("ldmatrix.sync.aligned.m8n8.x4.shared.b16 {%0,%1,%2,%3}, [%4];"
        : "=r"(r[0]), "=r"(r[1]), "=r"(r[2]), "=r"(r[3]) : "r"(addr));
}
__device__ __forceinline__ void cpa16(uint32_t dst, const void* src, int srcsz) {
    asm volatile("cp.async.ca.shared.global [%0], [%1], 16, %2;"
        :: "r"(dst), "l"(src), "r"(srcsz) : "memory");
}
__device__ __forceinline__ void cpa_commit() {
    asm volatile("cp.async.commit_group;" ::: "memory");
}
// fp32 pair -> bf16x2 hi + bf16x2 lo (residual)
__device__ __forceinline__ void cvt_hl(float2 v, uint32_t& hi, uint32_t& lo) {
    __nv_bfloat162 h = __floats2bfloat162_rn(v.x, v.y);
    __nv_bfloat162 l = __floats2bfloat162_rn(v.x - __bfloat162float(h.x),
                                             v.y - __bfloat162float(h.y));
    hi = *(uint32_t*)&h;
    lo = *(uint32_t*)&l;
}

// ---------------- pass 3: cp.async double-buffered HMMA GEMM ----------------
// A staged as raw fp32; fragments built in registers (LDS.64 + cvt).
__global__ void __launch_bounds__(NTHREADS, 2)
k_gemm(const float* __restrict__ x, const float* __restrict__ b,
       float* __restrict__ out) {
    extern __shared__ char smem[];
    const int tid = threadIdx.x;
    const int wid = tid >> 5;
    const int lid = tid & 31;
    const int g4 = lid >> 2;
    const int q4 = lid & 3;

    const int src   = blockIdx.x >> 6;
    const int local = blockIdx.x & (TILES_PER_SRC - 1);
    const int count = g_cursor[src * 32] - src * CAP;
    if (local * BM >= count) return;

    int* sperm = (int*)(smem + SM_PERM);
    const int myprow = g_perm[src * CAP + local * BM + tid];
    sperm[tid] = myprow;

    const uint32_t smb = (uint32_t)__cvta_generic_to_shared(smem);
    const uint32_t stage0 = smb + SM_STAGE;
    char* const stage0g = smem + SM_STAGE;

    // ---- stage issuer: chunk c into buffer buf ----
    // A: thread tid owns row tid -> 16 x 16B granules (contiguous 256B of x row)
    // B: 4 granules per split per thread
    auto issue = [&](int c, int buf) {
        const uint32_t bs = stage0 + buf * STAGE_BYTES;
        const int sz = (myprow >= 0) ? 16 : 0;
        const char* gsrc = (const char*)(x + (size_t)(myprow >= 0 ? myprow : 0) * F_IN + c * BK);
        const uint32_t adst = bs + OFF_A + tid * ASB;
        #pragma unroll
        for (int g = 0; g < 16; g++)
            cpa16(adst + g * 16, gsrc + g * 16, sz);
        #pragma unroll
        for (int q = 0; q < 4; q++) {
            int i = q * NTHREADS + tid;
            int n = i >> 3, g = i & 7;
            size_t gb = ((size_t)(src * F_OUT + n) * F_IN + c * BK) * 2 + g * 16;
            uint32_t dst = bs + n * SB + g * 16;
            cpa16(dst + OFF_BHI, (const char*)g_Whi + gb, 16);
            cpa16(dst + OFF_BLO, (const char*)g_Wlo + gb, 16);
        }
        cpa_commit();
    };

    float acc[2][8][4];
    #pragma unroll
    for (int mb = 0; mb < 2; mb++)
        #pragma unroll
        for (int nb = 0; nb < 8; nb++)
            #pragma unroll
            for (int j = 0; j < 4; j++) acc[mb][nb][j] = 0.0f;

    // ldmatrix lane offset for B (unchanged from validated R5 path)
    const uint32_t offB = ((lid & 7) + ((lid >> 4) & 1) * 8) * SB + ((lid >> 3) & 1) * 16;

    issue(0, 0);

    #pragma unroll
    for (int c = 0; c < CHUNKS; c++) {
        if (c + 1 < CHUNKS) {
            issue(c + 1, (c + 1) & 1);
            asm volatile("cp.async.wait_group 1;" ::: "memory");
        } else {
            asm volatile("cp.async.wait_group 0;" ::: "memory");
        }
        __syncthreads();

        const char* bufg = stage0g + (c & 1) * STAGE_BYTES;
        const uint32_t bsu = stage0 + (c & 1) * STAGE_BYTES;
        const uint32_t bHiB = bsu + OFF_BHI, bLoB = bsu + OFF_BLO;

        #pragma unroll
        for (int ks = 0; ks < 4; ks++) {
            // A fragments from fp32 smem, converted in registers
            uint32_t ahi[2][4], alo[2][4];
            #pragma unroll
            for (int mb = 0; mb < 2; mb++) {
                const char* ab = bufg + OFF_A +
                    (uint32_t)(wid * 32 + mb * 16 + g4) * ASB + ks * 64 + q4 * 8;
                float2 f0 = *(const float2*)(ab);                 // (g4,    2q4..+1)
                float2 f1 = *(const float2*)(ab + 8 * ASB);       // (g4+8,  2q4..+1)
                float2 f2 = *(const float2*)(ab + 32);            // (g4,    2q4+8..+9)
                float2 f3 = *(const float2*)(ab + 8 * ASB + 32);  // (g4+8,  2q4+8..+9)
                cvt_hl(f0, ahi[mb][0], alo[mb][0]);
                cvt_hl(f1, ahi[mb][1], alo[mb][1]);
                cvt_hl(f2, ahi[mb][2], alo[mb][2]);
                cvt_hl(f3, ahi[mb][3], alo[mb][3]);
            }
            #pragma unroll
            for (int p = 0; p < 4; p++) {
                uint32_t bo = (uint32_t)(p * 16) * SB + ks * 32 + offB;
                uint32_t bhi[4], blo[4];
                ldm_x4(bhi, bHiB + bo);
                ldm_x4(blo, bLoB + bo);
                #pragma unroll
                for (int mb = 0; mb < 2; mb++) {
                    mma_bf16(acc[mb][p * 2 + 0], ahi[mb], bhi[0], bhi[1]);
                    mma_bf16(acc[mb][p * 2 + 1], ahi[mb], bhi[2], bhi[3]);
                    mma_bf16(acc[mb][p * 2 + 0], ahi[mb], blo[0], blo[1]);
                    mma_bf16(acc[mb][p * 2 + 1], ahi[mb], blo[2], blo[3]);
                    mma_bf16(acc[mb][p * 2 + 0], alo[mb], bhi[0], bhi[1]);
                    mma_bf16(acc[mb][p * 2 + 1], alo[mb], bhi[2], bhi[3]);
                }
            }
        }
        __syncthreads();
    }

    // epilogue: bias + scattered store
    #pragma unroll
    for (int nb = 0; nb < 8; nb++) {
        int col = nb * 8 + q4 * 2;
        float2 bv = *(const float2*)(b + src * F_OUT + col);
        #pragma unroll
        for (int mb = 0; mb < 2; mb++) {
            #pragma unroll
            for (int half = 0; half < 2; half++) {
                int r = wid * 32 + mb * 16 + g4 + half * 8;
                int prow = sperm[r];
                if (prow >= 0) {
                    float2 o;
                    o.x = acc[mb][nb][half * 2 + 0] + bv.x;
                    o.y = acc[mb][nb][half * 2 + 1] + bv.y;
                    *(float2*)(out + (size_t)prow * F_OUT + col) = o;
                }
            }
        }
    }
}

// ---------------- launch ----------------
extern "C" void kernel_launch(void* const* d_in, const int* in_sizes, int n_in,
                              void* d_out, int out_size) {
    const float* x   = (const float*)d_in[0];
    const int*   src = (const int*)d_in[1];
    const float* W   = (const float*)d_in[2];
    const float* b   = (const float*)d_in[3];
    float* out = (float*)d_out;

    cudaFuncSetAttribute(k_gemm, cudaFuncAttributeMaxDynamicSharedMemorySize, SM_TOTAL);

    k_init<<<(N_SRC * CAP / 4) / 256, 256>>>();
    k_scatter<<<N_ROWS / (256 * 4), 256>>>(src);
    k_prepW<<<N_SRC * CHUNKS, 256>>>(W);
    k_gemm<<<GRID_GEMM, NTHREADS, SM_TOTAL>>>(x, b, out);
}

// round 8
// speedup vs baseline: 5.1127x; 1.2872x over previous
#include <cuda_runtime.h>
#include <cuda_bf16.h>
#include <cstdint>

// ---------------- problem constants ----------------
#define N_ROWS 131072
#define F_IN   256
#define N_SRC  32
#define F_OUT  64
#define W_COLS (N_SRC * F_OUT)   // 2048

#define BM 128
#define BK 32
#define CHUNKS (F_IN / BK)       // 8
#define NTHREADS 256
#define CAP 8192
#define TILES_PER_SRC (CAP / BM) // 64
#define GRID_GEMM (N_SRC * TILES_PER_SRC)  // 2048

// stage layout (per buffer):
//   A: 128 rows x 160B (32 fp32 + 8 pad floats) -> conflict-free LDS.64 frags
//   Bhi/Blo: 64 rows x 80B (32 bf16 + 8 pad)    -> conflict-free ldmatrix
#define ASB 160
#define SB  80
#define A_BYTES (BM * ASB)             // 20480
#define B_BYTES (F_OUT * SB)           // 5120
#define OFF_A   0
#define OFF_BHI A_BYTES
#define OFF_BLO (A_BYTES + B_BYTES)
#define STAGE_BYTES (A_BYTES + 2 * B_BYTES)   // 30720
#define SM_PERM 0
#define SM_STAGE 512
#define SM_TOTAL (SM_STAGE + 2 * STAGE_BYTES) // 61952

// ---------------- device scratch ----------------
__device__ int g_cursor[N_SRC * 32];
__device__ int g_perm[N_SRC * CAP];
__device__ __nv_bfloat16 g_Whi[N_SRC * F_OUT * F_IN];  // [src][n][k]
__device__ __nv_bfloat16 g_Wlo[N_SRC * F_OUT * F_IN];

// ---------------- pass 0: reset ----------------
__global__ void k_init() {
    int i = blockIdx.x * blockDim.x + threadIdx.x;
    ((int4*)g_perm)[i] = make_int4(-1, -1, -1, -1);
    if (i < N_SRC) g_cursor[i * 32] = i * CAP;
}

// ---------------- pass 1: scatter (warp-aggregated, ILP=4) ----------------
__global__ void k_scatter(const int* __restrict__ src) {
    int i0 = (blockIdx.x * blockDim.x + threadIdx.x) * 4;
    int4 s4 = *(const int4*)(src + i0);
    int sv[4] = { s4.x, s4.y, s4.z, s4.w };
    int lane = threadIdx.x & 31;
    #pragma unroll
    for (int j = 0; j < 4; j++) {
        int s = sv[j];
        unsigned m = __match_any_sync(0xffffffffu, s);
        int leader = __ffs(m) - 1;
        int rank = __popc(m & ((1u << lane) - 1));
        int base = 0;
        if (lane == leader) base = atomicAdd(&g_cursor[s * 32], __popc(m));
        base = __shfl_sync(0xffffffffu, base, leader);
        g_perm[base + rank] = i0 + j;
    }
}

// ---------------- pass 2: W -> [src][n][k] bf16 hi/lo ----------------
__global__ void k_prepW(const float* __restrict__ W) {
    __shared__ float tile[64][65];
    const int s = blockIdx.x >> 2;
    const int c = blockIdx.x & 3;
    const int tid = threadIdx.x;
    #pragma unroll
    for (int q = 0; q < 16; q++) {
        int idx = q * 256 + tid;
        int kk = idx >> 6, n = idx & 63;
        tile[kk][n] = W[(size_t)(c * 64 + kk) * W_COLS + s * F_OUT + n];
    }
    __syncthreads();
    #pragma unroll
    for (int q = 0; q < 16; q++) {
        int idx = q * 256 + tid;
        int n = idx >> 6, kk = idx & 63;
        float v = tile[kk][n];
        __nv_bfloat16 hi = __float2bfloat16(v);
        __nv_bfloat16 lo = __float2bfloat16(v - __bfloat162float(hi));
        size_t o = (size_t)(s * F_OUT + n) * F_IN + c * 64 + kk;
        g_Whi[o] = hi;
        g_Wlo[o] = lo;
    }
}

// ---------------- wrappers ----------------
__device__ __forceinline__ void mma_bf16(float* c, const uint32_t* a,
                                         uint32_t b0, uint32_t b1) {
    asm volatile(
        "mma.sync.aligned.m16n8k16.row.col.f32.bf16.bf16.f32 "
        "{%0,%1,%2,%3}, {%4,%5,%6,%7}, {%8,%9}, {%0,%1,%2,%3};"
        : "+f"(c[0]), "+f"(c[1]), "+f"(c[2]), "+f"(c[3])
        : "r"(a[0]), "r"(a[1]), "r"(a[2]), "r"(a[3]), "r"(b0), "r"(b1));
}
__device__ __forceinline__ void ldm_x4(uint32_t* r, uint32_t addr) {
    asm volatile("ldmatrix.sync.aligned.m8n8.x4.shared.b16 {%0,%1,%2,%3}, [%4];"
        : "=r"(r[0]), "=r"(r[1]), "=r"(r[2]), "=r"(r[3]) : "r"(addr));
}
__device__ __forceinline__ void cpa16(uint32_t dst, const void* src, int srcsz) {
    asm volatile("cp.async.ca.shared.global [%0], [%1], 16, %2;"
        :: "r"(dst), "l"(src), "r"(srcsz) : "memory");
}
__device__ __forceinline__ void cpa_commit() {
    asm volatile("cp.async.commit_group;" ::: "memory");
}
__device__ __forceinline__ void cvt_hl(float2 v, uint32_t& hi, uint32_t& lo) {
    __nv_bfloat162 h = __floats2bfloat162_rn(v.x, v.y);
    __nv_bfloat162 l = __floats2bfloat162_rn(v.x - __bfloat162float(h.x),
                                             v.y - __bfloat162float(h.y));
    hi = *(uint32_t*)&h;
    lo = *(uint32_t*)&l;
}

// ---------------- pass 3: cp.async double-buffered HMMA GEMM ----------------
// 256 threads / 8 warps; warp w computes rows w*16..w*16+15 x all 64 cols.
__global__ void __launch_bounds__(NTHREADS, 3)
k_gemm(const float* __restrict__ x, const float* __restrict__ b,
       float* __restrict__ out) {
    extern __shared__ char smem[];
    const int tid = threadIdx.x;
    const int wid = tid >> 5;
    const int lid = tid & 31;
    const int g4 = lid >> 2;
    const int q4 = lid & 3;

    const int src   = blockIdx.x >> 6;
    const int local = blockIdx.x & (TILES_PER_SRC - 1);
    const int count = g_cursor[src * 32] - src * CAP;
    if (local * BM >= count) return;

    int* sperm = (int*)(smem + SM_PERM);
    if (tid < BM) sperm[tid] = g_perm[src * CAP + local * BM + tid];
    __syncthreads();

    const uint32_t smb = (uint32_t)__cvta_generic_to_shared(smem);
    const uint32_t stage0 = smb + SM_STAGE;
    char* const stage0g = smem + SM_STAGE;

    // A staging: 2 threads per row; 4 granules each
    const int arow = tid >> 1;
    const int ahalf = tid & 1;
    const int aprow = sperm[arow];

    // B staging: 256 granules per split (64 rows x 4); exactly 1 per thread
    const int bn = tid >> 2;
    const int bg = tid & 3;

    // ---- stage issuer: chunk c into buffer buf ----
    auto issue = [&](int c, int buf) {
        const uint32_t bs = stage0 + buf * STAGE_BYTES;
        const int sz = (aprow >= 0) ? 16 : 0;
        const char* gsrc = (const char*)(x + (size_t)(aprow >= 0 ? aprow : 0) * F_IN + c * BK)
                         + ahalf * 64;
        const uint32_t adst = bs + OFF_A + arow * ASB + ahalf * 64;
        #pragma unroll
        for (int g = 0; g < 4; g++)
            cpa16(adst + g * 16, gsrc + g * 16, sz);
        {
            size_t gb = ((size_t)(src * F_OUT + bn) * F_IN + c * BK) * 2 + bg * 16;
            uint32_t dst = bs + bn * SB + bg * 16;
            cpa16(dst + OFF_BHI, (const char*)g_Whi + gb, 16);
            cpa16(dst + OFF_BLO, (const char*)g_Wlo + gb, 16);
        }
        cpa_commit();
    };

    float acc[8][4];
    #pragma unroll
    for (int nb = 0; nb < 8; nb++)
        #pragma unroll
        for (int j = 0; j < 4; j++) acc[nb][j] = 0.0f;

    const uint32_t offB = ((lid & 7) + ((lid >> 4) & 1) * 8) * SB + ((lid >> 3) & 1) * 16;

    issue(0, 0);

    #pragma unroll 1
    for (int c = 0; c < CHUNKS; c++) {
        if (c + 1 < CHUNKS) {
            issue(c + 1, (c + 1) & 1);
            asm volatile("cp.async.wait_group 1;" ::: "memory");
        } else {
            asm volatile("cp.async.wait_group 0;" ::: "memory");
        }
        __syncthreads();

        const char* bufg = stage0g + (c & 1) * STAGE_BYTES;
        const uint32_t bsu = stage0 + (c & 1) * STAGE_BYTES;
        const uint32_t bHiB = bsu + OFF_BHI, bLoB = bsu + OFF_BLO;

        #pragma unroll
        for (int ks = 0; ks < 2; ks++) {
            // A fragment (16 rows x k16) from fp32 smem, converted in registers
            uint32_t ahi[4], alo[4];
            {
                const char* ab = bufg + OFF_A +
                    (uint32_t)(wid * 16 + g4) * ASB + ks * 64 + q4 * 8;
                float2 f0 = *(const float2*)(ab);
                float2 f1 = *(const float2*)(ab + 8 * ASB);
                float2 f2 = *(const float2*)(ab + 32);
                float2 f3 = *(const float2*)(ab + 8 * ASB + 32);
                cvt_hl(f0, ahi[0], alo[0]);
                cvt_hl(f1, ahi[1], alo[1]);
                cvt_hl(f2, ahi[2], alo[2]);
                cvt_hl(f3, ahi[3], alo[3]);
            }
            #pragma unroll
            for (int p = 0; p < 4; p++) {
                uint32_t bo = (uint32_t)(p * 16) * SB + ks * 32 + offB;
                uint32_t bhi[4], blo[4];
                ldm_x4(bhi, bHiB + bo);
                ldm_x4(blo, bLoB + bo);
                mma_bf16(acc[p * 2 + 0], ahi, bhi[0], bhi[1]);
                mma_bf16(acc[p * 2 + 1], ahi, bhi[2], bhi[3]);
                mma_bf16(acc[p * 2 + 0], ahi, blo[0], blo[1]);
                mma_bf16(acc[p * 2 + 1], ahi, blo[2], blo[3]);
                mma_bf16(acc[p * 2 + 0], alo, bhi[0], bhi[1]);
                mma_bf16(acc[p * 2 + 1], alo, bhi[2], bhi[3]);
            }
        }
        __syncthreads();
    }

    // epilogue: bias + scattered store
    #pragma unroll
    for (int nb = 0; nb < 8; nb++) {
        int col = nb * 8 + q4 * 2;
        float2 bv = *(const float2*)(b + src * F_OUT + col);
        #pragma unroll
        for (int half = 0; half < 2; half++) {
            int r = wid * 16 + g4 + half * 8;
            int prow = sperm[r];
            if (prow >= 0) {
                float2 o;
                o.x = acc[nb][half * 2 + 0] + bv.x;
                o.y = acc[nb][half * 2 + 1] + bv.y;
                *(float2*)(out + (size_t)prow * F_OUT + col) = o;
            }
        }
    }
}

// ---------------- launch ----------------
extern "C" void kernel_launch(void* const* d_in, const int* in_sizes, int n_in,
                              void* d_out, int out_size) {
    const float* x   = (const float*)d_in[0];
    const int*   src = (const int*)d_in[1];
    const float* W   = (const float*)d_in[2];
    const float* b   = (const float*)d_in[3];
    float* out = (float*)d_out;

    cudaFuncSetAttribute(k_gemm, cudaFuncAttributeMaxDynamicSharedMemorySize, SM_TOTAL);

    k_init<<<(N_SRC * CAP / 4) / 256, 256>>>();
    k_scatter<<<N_ROWS / (256 * 4), 256>>>(src);
    k_prepW<<<N_SRC * CHUNKS / 2, 256>>>(W);
    k_gemm<<<GRID_GEMM, NTHREADS, SM_TOTAL>>>(x, b, out);
}